// round 17
// baseline (speedup 1.0000x reference)
#include <cuda_runtime.h>
#include <cuda_bf16.h>
#include <math.h>
#include <stdint.h>

#define BB 4
#define NN 8192
#define CC 256
#define HH 8
#define DD 64
#define HD 512
#define NCHUNK 16
#define CHK (NN / NCHUNK)   // 512

typedef unsigned long long u64t;

// ---------------------------------------------------------------------------
// Scratch (__device__ globals; allocation-free rule)
// ---------------------------------------------------------------------------
__device__ float g_k[BB * HH * NN * DD];            // normed+roped K, [bh][n][d]
__device__ float g_v[BB * HH * NN * DD];            // normed V
__device__ float g_part[NCHUNK * BB * HH * DD * DD];
__device__ float g_dots[BB * HH * DD * DD];
__device__ float g_trig[NN * 64];                   // per n: cx[16] sx[16] cy[16] sy[16]

__device__ __nv_bfloat16 g_xh[32768 * 256];         // X split
__device__ __nv_bfloat16 g_xl[32768 * 256];
__device__ __nv_bfloat16 g_wh[1536 * 256];          // [Wq;Wk;Wv] split
__device__ __nv_bfloat16 g_wl[1536 * 256];
__device__ __nv_bfloat16 g_uh[32768 * 512];         // roped q split, [m][h*64+d]
__device__ __nv_bfloat16 g_ul[32768 * 512];
__device__ __nv_bfloat16 g_mah[BB * 256 * 512];     // A_b = dots x Wo, split
__device__ __nv_bfloat16 g_mal[BB * 256 * 512];

// ---------------------------------------------------------------------------
// helpers
// ---------------------------------------------------------------------------
__device__ __forceinline__ uint32_t smem_u32(const void* p) {
    uint32_t a;
    asm("{ .reg .u64 t; cvta.to.shared.u64 t, %1; cvt.u32.u64 %0, t; }" : "=r"(a) : "l"(p));
    return a;
}
__device__ __forceinline__ void ldm_x4(uint32_t& r0, uint32_t& r1, uint32_t& r2, uint32_t& r3,
                                       uint32_t addr) {
    asm volatile("ldmatrix.sync.aligned.m8n8.x4.shared.b16 {%0,%1,%2,%3}, [%4];"
                 : "=r"(r0), "=r"(r1), "=r"(r2), "=r"(r3) : "r"(addr));
}
__device__ __forceinline__ void mma_bf16(float* d, const uint32_t* a, const uint32_t* b) {
    asm volatile(
        "mma.sync.aligned.m16n8k16.row.col.f32.bf16.bf16.f32 "
        "{%0,%1,%2,%3}, {%4,%5,%6,%7}, {%8,%9}, {%0,%1,%2,%3};"
        : "+f"(d[0]), "+f"(d[1]), "+f"(d[2]), "+f"(d[3])
        : "r"(a[0]), "r"(a[1]), "r"(a[2]), "r"(a[3]), "r"(b[0]), "r"(b[1]));
}
// cp.async: global -> smem direct, bypassing the register file / L1 writeback.
__device__ __forceinline__ void cp_async16(uint32_t smem_addr, const void* gptr) {
    asm volatile("cp.async.cg.shared.global [%0], [%1], 16;"
                 :: "r"(smem_addr), "l"(gptr) : "memory");
}
#define CP_ASYNC_COMMIT() asm volatile("cp.async.commit_group;" ::: "memory")
#define CP_ASYNC_WAIT0()  asm volatile("cp.async.wait_group 0;" ::: "memory")
#define CP_ASYNC_WAIT1()  asm volatile("cp.async.wait_group 1;" ::: "memory")

// ---- packed f32x2 helpers (SIMT kernels) ----------------------------------
__device__ __forceinline__ u64t ffma2(u64t a, u64t b, u64t c) {
    u64t d;
    asm("fma.rn.f32x2 %0, %1, %2, %3;" : "=l"(d) : "l"(a), "l"(b), "l"(c));
    return d;
}
__device__ __forceinline__ u64t pack2(float x) {
    u64t d;
    asm("mov.b64 %0, {%1, %1};" : "=l"(d) : "r"(__float_as_uint(x)));
    return d;
}
__device__ __forceinline__ void unpack2(u64t v, float& lo, float& hi) {
    unsigned a, b;
    asm("mov.b64 {%0, %1}, %2;" : "=r"(a), "=r"(b) : "l"(v));
    lo = __uint_as_float(a);
    hi = __uint_as_float(b);
}
__device__ __forceinline__ void bf16split(float x, __nv_bfloat16& h, __nv_bfloat16& l) {
    h = __float2bfloat16_rn(x);
    l = __float2bfloat16_rn(x - __bfloat162float(h));
}
__device__ __forceinline__ void split_pack4(const float* v, uint2& ph, uint2& pl) {
    __nv_bfloat16 h0, l0, h1, l1, h2, l2, h3, l3;
    bf16split(v[0], h0, l0); bf16split(v[1], h1, l1);
    bf16split(v[2], h2, l2); bf16split(v[3], h3, l3);
    ph.x = (uint32_t)__bfloat16_as_ushort(h0) | ((uint32_t)__bfloat16_as_ushort(h1) << 16);
    ph.y = (uint32_t)__bfloat16_as_ushort(h2) | ((uint32_t)__bfloat16_as_ushort(h3) << 16);
    pl.x = (uint32_t)__bfloat16_as_ushort(l0) | ((uint32_t)__bfloat16_as_ushort(l1) << 16);
    pl.y = (uint32_t)__bfloat16_as_ushort(l2) | ((uint32_t)__bfloat16_as_ushort(l3) << 16);
}

// ---------------------------------------------------------------------------
// trig table
// ---------------------------------------------------------------------------
__global__ __launch_bounds__(256) void trig_init(const float* __restrict__ pos)
{
    const int idx = blockIdx.x * 256 + threadIdx.x;
    const int n = idx >> 4;
    const int j = idx & 15;
    const float invf = exp2f(-(float)j * (13.2877123795494f / 16.0f));
    const float px = pos[n * 2 + 0];
    const float py = pos[n * 2 + 1];
    float cx, sx, cy, sy;
    sincosf(px * 64.0f * invf, &sx, &cx);
    sincosf(py * 64.0f * invf, &sy, &cy);
    float* T = &g_trig[(size_t)n * 64];
    T[j] = cx; T[16 + j] = sx; T[32 + j] = cy; T[48 + j] = sy;
}

// ---------------------------------------------------------------------------
// prep: split X and qkv-weights into bf16 hi/lo
// ---------------------------------------------------------------------------
__global__ __launch_bounds__(256) void prep_x(const float* __restrict__ X)
{
    const size_t i4 = ((size_t)blockIdx.x * 256 + threadIdx.x) * 4;
    float4 v = *(const float4*)&X[i4];
    uint2 ph, pl;
    split_pack4((const float*)&v, ph, pl);
    *(uint2*)&g_xh[i4] = ph;
    *(uint2*)&g_xl[i4] = pl;
}

__global__ __launch_bounds__(256) void prep_w(
    const float* __restrict__ Wq, const float* __restrict__ Wk,
    const float* __restrict__ Wv)
{
    const size_t i4 = ((size_t)blockIdx.x * 256 + threadIdx.x) * 4;   // < 393216
    int seg = (int)(i4 / 131072);
    size_t off = i4 % 131072;
    const float* src = (seg == 0) ? Wq : (seg == 1) ? Wk : Wv;
    __nv_bfloat16* dh = g_wh + (size_t)seg * 131072;
    __nv_bfloat16* dl = g_wl + (size_t)seg * 131072;
    float4 v = *(const float4*)&src[off];
    uint2 ph, pl;
    split_pack4((const float*)&v, ph, pl);
    *(uint2*)&dh[off] = ph;
    *(uint2*)&dl[off] = pl;
}

// ---------------------------------------------------------------------------
// HMMA GEMM (R14 mainloop: double-buffered cp.async, K stage = 16):
//   D = Ah*Bh + Al*Bh + Ah*Bl   (bf16 2-term split, lo*lo dropped)
// Block tile 128(J) x 128(tok). 8 warps = 4(m) x 2(n), warp 32x64.
// MODE 0: A = W_cat, B = X.  Epilogue FUSES: q -> rope -> bf16 split (g_uh/ul);
//         k -> inst-norm+rope -> g_k; v -> inst-norm -> g_v.
// MODE 1: A = A_b (dots x Wo, per batch), B = q split -> out + bias
// ---------------------------------------------------------------------------
template <int MODE>
__global__ __launch_bounds__(256, 2) void gemm_mma(const float* __restrict__ bias,
                                                   float* __restrict__ outp)
{
    constexpr int KTOT = (MODE == 0) ? 256 : 512;
    constexpr int NSTAGE = KTOT / 16;
    constexpr int ST = 40;                 // bf16 per combined row (16 hi + 16 lo + 8 pad)
    constexpr int SLAB = 128 * ST;         // elems per slab (A or B): 5120 (10240 B)
    constexpr int BUFB = 4 * SLAB;         // BYTES per buffer (A+B): 20480

    __shared__ __align__(16) __nv_bfloat16 smem[4 * SLAB];   // 40960 B (2 buffers)

    const int tid = threadIdx.x;
    const int wid = tid >> 5;
    const int lane = tid & 31;
    const int wm = wid & 3;        // warp m (J) index: 4
    const int wn = wid >> 2;       // warp n (tok) index: 2
    const int J0 = blockIdx.x * 128;
    const int T0 = blockIdx.y * 128;

    float acc[2][8][4];
    #pragma unroll
    for (int am = 0; am < 2; am++)
        #pragma unroll
        for (int bn = 0; bn < 8; bn++)
            #pragma unroll
            for (int c = 0; c < 4; c++) acc[am][bn][c] = 0.0f;

    const int lrow = tid >> 1;       // 0..127
    const int lhalf = tid & 1;       // 16B half of the 32B hi (or lo) row chunk

    // global source pointers
    const __nv_bfloat16 *Ah, *Al, *Bh, *Bl;
    if (MODE == 0) { Ah = g_wh; Al = g_wl; Bh = g_xh; Bl = g_xl; }
    else {
        const int bb_ = T0 >> 13;
        Ah = g_mah + (size_t)bb_ * (256 * 512);
        Al = g_mal + (size_t)bb_ * (256 * 512);
        Bh = g_uh; Bl = g_ul;
    }
    const __nv_bfloat16* gA_h = Ah + (size_t)(J0 + lrow) * KTOT + lhalf * 8;
    const __nv_bfloat16* gA_l = Al + (size_t)(J0 + lrow) * KTOT + lhalf * 8;
    const __nv_bfloat16* gB_h = Bh + (size_t)(T0 + lrow) * KTOT + lhalf * 8;
    const __nv_bfloat16* gB_l = Bl + (size_t)(T0 + lrow) * KTOT + lhalf * 8;

    // store-side smem byte addresses (buffer 0)
    const uint32_t smb = smem_u32(smem);
    const uint32_t stA = smb + (uint32_t)(lrow * ST * 2) + lhalf * 16;      // hi chunk
    const uint32_t stB = stA + (uint32_t)(SLAB * 2);                         // B slab

    // fragment smem byte addresses (buffer 0)
    const int ar = wm * 32 + (lane & 15);
    const int ac = (lane >> 4) << 3;
    const uint32_t aAh0 = smb + (uint32_t)((ar * ST + ac) * 2);
    const uint32_t aAh1 = smb + (uint32_t)(((ar + 16) * ST + ac) * 2);
    const uint32_t aAl0 = aAh0 + 32;
    const uint32_t aAl1 = aAh1 + 32;
    const int br = wn * 64 + ((lane >> 4) << 3) + (lane & 7);
    const int bc = ((lane >> 3) & 1) << 3;
    const uint32_t aBh = smb + (uint32_t)(SLAB * 2) + (uint32_t)((br * ST + bc) * 2);
    const uint32_t aBl = aBh + 32;

    // prologue: stage 0 into buffer 0
    {
        cp_async16(stA,      gA_h);
        cp_async16(stA + 32, gA_l);
        cp_async16(stB,      gB_h);
        cp_async16(stB + 32, gB_l);
        CP_ASYNC_COMMIT();
    }

    for (int s = 0; s < NSTAGE; s++) {
        if (s + 1 < NSTAGE) {
            const uint32_t bo = ((s + 1) & 1) * BUFB;
            const int kn = (s + 1) * 16;
            cp_async16(stA + bo,      gA_h + kn);
            cp_async16(stA + bo + 32, gA_l + kn);
            cp_async16(stB + bo,      gB_h + kn);
            cp_async16(stB + bo + 32, gB_l + kn);
            CP_ASYNC_COMMIT();
            CP_ASYNC_WAIT1();
        } else {
            CP_ASYNC_WAIT0();
        }
        __syncthreads();

        const uint32_t bo = (s & 1) * BUFB;
        uint32_t ah[2][4], al[2][4];
        ldm_x4(ah[0][0], ah[0][1], ah[0][2], ah[0][3], aAh0 + bo);
        ldm_x4(ah[1][0], ah[1][1], ah[1][2], ah[1][3], aAh1 + bo);
        ldm_x4(al[0][0], al[0][1], al[0][2], al[0][3], aAl0 + bo);
        ldm_x4(al[1][0], al[1][1], al[1][2], al[1][3], aAl1 + bo);
        #pragma unroll
        for (int h2 = 0; h2 < 2; h2++) {     // bn half: fragments 4*h2 .. 4*h2+3
            uint32_t bb[4][2];
            #pragma unroll
            for (int j = 0; j < 2; j++)
                ldm_x4(bb[2 * j][0], bb[2 * j][1], bb[2 * j + 1][0], bb[2 * j + 1][1],
                       aBh + bo + (2 * h2 + j) * 16 * ST * 2);
            #pragma unroll
            for (int am = 0; am < 2; am++)
                #pragma unroll
                for (int j4 = 0; j4 < 4; j4++)
                    mma_bf16(acc[am][4 * h2 + j4], ah[am], bb[j4]);
            #pragma unroll
            for (int am = 0; am < 2; am++)
                #pragma unroll
                for (int j4 = 0; j4 < 4; j4++)
                    mma_bf16(acc[am][4 * h2 + j4], al[am], bb[j4]);
            #pragma unroll
            for (int j = 0; j < 2; j++)
                ldm_x4(bb[2 * j][0], bb[2 * j][1], bb[2 * j + 1][0], bb[2 * j + 1][1],
                       aBl + bo + (2 * h2 + j) * 16 * ST * 2);
            #pragma unroll
            for (int am = 0; am < 2; am++)
                #pragma unroll
                for (int j4 = 0; j4 < 4; j4++)
                    mma_bf16(acc[am][4 * h2 + j4], ah[am], bb[j4]);
        }
        __syncthreads();
    }

    // Epilogue: two half-passes over tokens, staging transposed in smem.
    float* stage = (float*)smem;   // 64 x 132 fp32 = 33792 B (fits 40960)
    #pragma unroll 1
    for (int half = 0; half < 2; half++) {
        __syncthreads();
        if (wn == half) {
            #pragma unroll
            for (int am = 0; am < 2; am++)
                #pragma unroll
                for (int bn = 0; bn < 8; bn++)
                    #pragma unroll
                    for (int c = 0; c < 4; c++) {
                        const int ml = wm * 32 + am * 16 + (lane >> 2) + ((c >> 1) << 3);
                        const int nl = bn * 8 + (lane & 3) * 2 + (c & 1);
                        stage[nl * 132 + ml] = acc[am][bn][c];
                    }
        }
        __syncthreads();
        const int tok_l = tid >> 2;          // 0..63
        const int qg = tid & 3;              // 32-J group
        const float* srow = &stage[tok_l * 132 + qg * 32];
        const int m = T0 + half * 64 + tok_l;
        const int J = J0 + qg * 32;
        if (MODE == 0) {
            const int which = J >> 9;        // block-uniform (J0 mult of 128)
            const int h = (J >> 6) & 7;
            const int d0 = J & 63;           // 0 or 32
            const int b = m >> 13;
            const int n = m & (NN - 1);
            float v[32];
            #pragma unroll
            for (int i = 0; i < 32; i++) v[i] = srow[i];
            if (which == 0) {
                // Q: rope then bf16 split -> g_uh/g_ul [m][h*64+d]
                const float* T = &g_trig[(size_t)n * 64 + d0];
                float o[32];
                #pragma unroll
                for (int i = 0; i < 16; i++) {
                    const float cv = T[i], sv = T[16 + i];
                    o[i]      = v[i] * cv - v[i + 16] * sv;
                    o[i + 16] = v[i + 16] * cv + v[i] * sv;
                }
                const size_t off = (size_t)m * HD + h * DD + d0;
                #pragma unroll
                for (int dd = 0; dd < 32; dd += 4) {
                    uint2 ph, pl;
                    split_pack4(&o[dd], ph, pl);
                    *(uint2*)&g_uh[off + dd] = ph;
                    *(uint2*)&g_ul[off + dd] = pl;
                }
            } else {
                // K or V: instance norm across qg-partner (full 64-d row)
                float su = 0.0f, sq = 0.0f;
                #pragma unroll
                for (int i = 0; i < 32; i++) { su += v[i]; sq += v[i] * v[i]; }
                su += __shfl_xor_sync(0xffffffffu, su, 1);
                sq += __shfl_xor_sync(0xffffffffu, sq, 1);
                const float mean = su * (1.0f / 64.0f);
                const float inv = rsqrtf(sq * (1.0f / 64.0f) - mean * mean + 1e-5f);
                #pragma unroll
                for (int i = 0; i < 32; i++) v[i] = (v[i] - mean) * inv;
                float o[32];
                if (which == 1) {
                    const float* T = &g_trig[(size_t)n * 64 + d0];
                    #pragma unroll
                    for (int i = 0; i < 16; i++) {
                        const float cv = T[i], sv = T[16 + i];
                        o[i]      = v[i] * cv - v[i + 16] * sv;
                        o[i + 16] = v[i + 16] * cv + v[i] * sv;
                    }
                } else {
                    #pragma unroll
                    for (int i = 0; i < 32; i++) o[i] = v[i];
                }
                float* dst = ((which == 1) ? g_k : g_v)
                             + (((size_t)(b * HH + h)) * NN + n) * DD + d0;
                #pragma unroll
                for (int dd = 0; dd < 32; dd += 4)
                    *(float4*)&dst[dd] = *(const float4*)&o[dd];
            }
        } else {
            float* dst = outp + (size_t)m * CC + J;
            #pragma unroll
            for (int dd = 0; dd < 32; dd += 4) {
                float4 v = *(const float4*)&srow[dd];
                float4 bv = *(const float4*)&bias[J + dd];
                v.x += bv.x; v.y += bv.y; v.z += bv.z; v.w += bv.w;
                *(float4*)&dst[dd] = v;
            }
        }
    }
}

// ---------------------------------------------------------------------------
// kv_dots: pure partial K^T V per chunk (K,V already normed/roped by gemm0)
// ---------------------------------------------------------------------------
__global__ __launch_bounds__(256) void kv_dots()
{
    __shared__ __align__(16) float Ks[16][64];
    __shared__ __align__(16) float Vs[16][64];

    const int chunk = blockIdx.x;
    const int bh = blockIdx.y;
    const int tid = threadIdx.x;
    const int tx = tid & 15;
    const int ty = tid >> 4;
    const int lt = tid >> 4;
    const int ld4 = (tid & 15) * 4;

    const size_t nbase = (size_t)bh * NN + (size_t)chunk * CHK;

    u64t acc[4][2];
    #pragma unroll
    for (int i = 0; i < 4; i++) { acc[i][0] = 0ull; acc[i][1] = 0ull; }

    for (int s = 0; s < CHK; s += 16) {
        *(float4*)&Ks[lt][ld4] = *(const float4*)&g_k[(nbase + s + lt) * DD + ld4];
        *(float4*)&Vs[lt][ld4] = *(const float4*)&g_v[(nbase + s + lt) * DD + ld4];
        __syncthreads();

        #pragma unroll
        for (int t = 0; t < 16; t++) {
            float4 av = *(const float4*)&Ks[t][ty * 4];
            float4 wv = *(const float4*)&Vs[t][tx * 4];
            u64t w2[2];
            w2[0] = ((const u64t*)&wv)[0];
            w2[1] = ((const u64t*)&wv)[1];
            float a[4] = {av.x, av.y, av.z, av.w};
            #pragma unroll
            for (int i = 0; i < 4; i++) {
                u64t ap = pack2(a[i]);
                acc[i][0] = ffma2(ap, w2[0], acc[i][0]);
                acc[i][1] = ffma2(ap, w2[1], acc[i][1]);
            }
        }
        __syncthreads();
    }

    float* P = &g_part[((size_t)chunk * (BB * HH) + bh) * (DD * DD)];
    #pragma unroll
    for (int i = 0; i < 4; i++) {
        float4 ov;
        unpack2(acc[i][0], ov.x, ov.y);
        unpack2(acc[i][1], ov.z, ov.w);
        *(float4*)&P[(ty * 4 + i) * DD + tx * 4] = ov;
    }
}

__global__ __launch_bounds__(256) void reduce_dots()
{
    const int i = blockIdx.x * 256 + threadIdx.x;
    float s = 0.0f;
    #pragma unroll
    for (int c = 0; c < NCHUNK; c++)
        s += g_part[(size_t)c * (BB * HH * DD * DD) + i];
    g_dots[i] = s * (1.0f / (float)NN);
}

// ---------------------------------------------------------------------------
// make_M: A_b[c, h*64+d] = sum_e dots_bh[d, e] * Wo[c, h*64+e], bf16 split.
// One block per (b,h); thread = c.
// ---------------------------------------------------------------------------
__global__ __launch_bounds__(256) void make_M(const float* __restrict__ Wo)
{
    __shared__ float ds[64][64];           // dots_bh[d][e]
    const int bh = blockIdx.x;             // 0..31
    const int b = bh >> 3, h = bh & 7;
    const int tid = threadIdx.x;

    for (int i = tid; i < 4096; i += 256)
        ((float*)ds)[i] = g_dots[(size_t)bh * 4096 + i];
    __syncthreads();

    const int c = tid;                     // 0..255
    float wo[64];
    #pragma unroll
    for (int e = 0; e < 64; e += 4)
        *(float4*)&wo[e] = *(const float4*)&Wo[(size_t)c * HD + h * DD + e];

    const size_t base = (size_t)b * (256 * 512) + (size_t)c * HD + h * DD;
    for (int d = 0; d < 64; d += 4) {
        float r[4];
        #pragma unroll
        for (int j = 0; j < 4; j++) {
            float a = 0.0f;
            #pragma unroll 8
            for (int e = 0; e < 64; e++) a += ds[d + j][e] * wo[e];
            r[j] = a;
        }
        uint2 ph, pl;
        split_pack4(r, ph, pl);
        *(uint2*)&g_mah[base + d] = ph;
        *(uint2*)&g_mal[base + d] = pl;
    }
}

// ---------------------------------------------------------------------------
extern "C" void kernel_launch(void* const* d_in, const int* in_sizes, int n_in,
                              void* d_out, int out_size)
{
    const float* ux  = (const float*)d_in[0];
    const float* pos = (const float*)d_in[1];
    const float* Wq  = (const float*)d_in[2];
    const float* Wk  = (const float*)d_in[3];
    const float* Wv  = (const float*)d_in[4];
    const float* Wo  = (const float*)d_in[5];
    const float* bo  = (const float*)d_in[6];
    float* out = (float*)d_out;

    trig_init<<<(NN * 16) / 256, 256>>>(pos);
    prep_x<<<(32768 * 256) / (256 * 4), 256>>>(ux);
    prep_w<<<393216 / (256 * 4), 256>>>(Wq, Wk, Wv);
    gemm_mma<0><<<dim3(12, 256), 256>>>(nullptr, nullptr);
    kv_dots<<<dim3(NCHUNK, BB * HH), 256>>>();
    reduce_dots<<<(BB * HH * DD * DD) / 256, 256>>>();
    make_M<<<BB * HH, 256>>>(Wo);
    gemm_mma<1><<<dim3(2, 256), 256>>>(bo, out);
}